// round 11
// baseline (speedup 1.0000x reference)
#include <cuda_runtime.h>
#include <cstdint>

#define NODE_EMB 128
#define EDGE_EMB 16
#define D_IN     160      // 128 + 2*16
#define N_MAX    100000

#define TILE_N   128
#define MLP_T    512          // MLP threads (warps 0-15)
#define SC_T     128          // scatter threads (warps 16-19)
#define THREADS  (MLP_T + SC_T)
#define AS_STRIDE 132
#define GRID_F   148

// Scratch accumulators (device globals — no cudaMalloc allowed)
__device__ float g_rec [N_MAX * EDGE_EMB];
__device__ float g_sent[N_MAX * EDGE_EMB];
__device__ float g_rcnt[N_MAX];
__device__ float g_scnt[N_MAX];

// ---------------- packed f32x2 helpers (sm_100+) ----------------
__device__ __forceinline__ unsigned long long pack2(float lo, float hi) {
    unsigned long long r;
    asm("mov.b64 %0, {%1, %2};" : "=l"(r) : "f"(lo), "f"(hi));
    return r;
}
__device__ __forceinline__ unsigned long long bcast2(float v) {
    unsigned long long r;
    asm("mov.b64 %0, {%1, %1};" : "=l"(r) : "f"(v));
    return r;
}
__device__ __forceinline__ void fma2(unsigned long long& d,
                                     unsigned long long a,
                                     unsigned long long b) {
    asm("fma.rn.f32x2 %0, %1, %2, %0;" : "+l"(d) : "l"(a), "l"(b));
}
__device__ __forceinline__ void unpack2(unsigned long long v, float& lo, float& hi) {
    asm("mov.b64 {%0, %1}, %2;" : "=f"(lo), "=f"(hi) : "l"(v));
}
__device__ __forceinline__ void red4(float* p, float4 v) {
    asm volatile("red.global.add.v4.f32 [%0], {%1, %2, %3, %4};"
                 :: "l"(p), "f"(v.x), "f"(v.y), "f"(v.z), "f"(v.w) : "memory");
}
// Named barrier for the 512 MLP threads only (id 1) — scatter warps never touch it.
__device__ __forceinline__ void mlp_bar() {
    asm volatile("bar.sync 1, %0;" :: "r"(MLP_T) : "memory");
}

// ---------------- kernel 1: zero accumulators ----------------
__global__ void zero_kernel(int N) {
    int stride = gridDim.x * blockDim.x;
    int t = blockIdx.x * blockDim.x + threadIdx.x;
    int total4 = N * EDGE_EMB / 4;
    float4 z = make_float4(0.f, 0.f, 0.f, 0.f);
    for (int i = t; i < total4; i += stride) {
        reinterpret_cast<float4*>(g_rec)[i]  = z;
        reinterpret_cast<float4*>(g_sent)[i] = z;
    }
    for (int i = t; i < N; i += stride) {
        g_rcnt[i] = 0.f;
        g_scnt[i] = 0.f;
    }
}

// ---------------- kernel 2: co-resident scatter + MLP (warp-specialized) ----------------
// Warps 0-15 (512 thr): persistent fused concat+MLP (R10 scheme, named barrier).
// Warps 16-19 (128 thr): grid-stride dual scatter-sum (red.v4) — highest wids, so the
// hi-wid-first arbiter keeps the L2 atomic stream fed while MLP warps fill the FMA pipe.
__global__ __launch_bounds__(THREADS, 1)
void fused_kernel(const float* __restrict__ x,
                  const int* __restrict__ ei,
                  const float4* __restrict__ attr4,
                  const float* __restrict__ W1,
                  const float* __restrict__ b1,
                  const float* __restrict__ W2,
                  const float* __restrict__ b2,
                  float* __restrict__ out,
                  int E, int N, int np) {
    int tid = threadIdx.x;

    if (tid >= MLP_T) {
        // ======== scatter role ========
        int st = blockIdx.x * SC_T + (tid - MLP_T);
        int stride = GRID_F * SC_T;
        for (int e = st; e < E; e += stride) {
            int row = ei[e];        // receiver
            int col = ei[E + e];    // sender
            float4 v0 = attr4[(size_t)e * 4 + 0];
            float4 v1 = attr4[(size_t)e * 4 + 1];
            float4 v2 = attr4[(size_t)e * 4 + 2];
            float4 v3 = attr4[(size_t)e * 4 + 3];
            float* pr = &g_rec [(size_t)row * EDGE_EMB];
            float* ps = &g_sent[(size_t)col * EDGE_EMB];
            red4(pr + 0, v0); red4(pr + 4, v1); red4(pr + 8, v2); red4(pr + 12, v3);
            red4(ps + 0, v0); red4(ps + 4, v1); red4(ps + 8, v2); red4(ps + 12, v3);
            atomicAdd(&g_rcnt[row], 1.0f);
            atomicAdd(&g_scnt[col], 1.0f);
        }
        return;
    }

    // ======== MLP role (threads 0..511) ========
    extern __shared__ float smem_f[];
    float* As  = smem_f;                        // [D_IN][AS_STRIDE] transposed A / h
    float* W1s = As + D_IN * AS_STRIDE;         // [160][128]
    float* W2s = W1s + D_IN * NODE_EMB;         // [128][128]

    int tx = tid & 31;
    int ty = tid >> 5;

    for (int i = tid; i < (D_IN * NODE_EMB) / 4; i += MLP_T)
        reinterpret_cast<float4*>(W1s)[i] = reinterpret_cast<const float4*>(W1)[i];
    for (int i = tid; i < (NODE_EMB * NODE_EMB) / 4; i += MLP_T)
        reinterpret_cast<float4*>(W2s)[i] = reinterpret_cast<const float4*>(W2)[i];

    unsigned long long bias1[4], bias2[4];
    #pragma unroll
    for (int cc = 0; cc < 4; ++cc) {
        bias1[cc] = bcast2(b1[tx + 32 * cc]);
        bias2[cc] = bcast2(b2[tx + 32 * cc]);
    }

    for (int tile = blockIdx.x; tile < np; tile += GRID_F) {
        int node0 = tile * TILE_N;
        mlp_bar();   // previous tile's reads of As complete (incl. weight staging on iter 0)

        // Stage A^T: concat(x, rec_mean, sent_mean), transposed [k][node].
        // NOTE: MLP consumes pre-scatter means only at graph-replay level? No — the harness
        // runs zero+scatter to completion? They are separate kernel launches in-stream:
        // scatter finished before this kernel? It has NOT (fused). Correctness requires the
        // mean inputs; but this kernel also DOES the scatter concurrently... so the MLP must
        // not read g_rec until scatter done. We handle this by processing x-part here and
        // deferring mean-dependent part? -- NO: see launch order below; scatter_kernel runs
        // BEFORE fused_kernel for the mean-critical data. The in-kernel scatter warps here
        // process the NEXT-iteration? They process nothing: E passed as 0. (kept for layout)
        for (int idx = tid; idx < TILE_N * D_IN; idx += MLP_T) {
            int nl = idx / D_IN;
            int k  = idx - nl * D_IN;
            int n  = node0 + nl;
            float v = 0.f;
            if (n < N) {
                if (k < NODE_EMB) {
                    v = x[(size_t)n * NODE_EMB + k];
                } else if (k < NODE_EMB + EDGE_EMB) {
                    float c = g_rcnt[n];
                    v = g_rec[n * EDGE_EMB + (k - NODE_EMB)] / fmaxf(c, 1.f);
                } else {
                    float c = g_scnt[n];
                    v = g_sent[n * EDGE_EMB + (k - NODE_EMB - EDGE_EMB)] / fmaxf(c, 1.f);
                }
            }
            As[k * AS_STRIDE + nl] = v;
        }
        mlp_bar();

        unsigned long long acc[4][4];
        #pragma unroll
        for (int cc = 0; cc < 4; ++cc) {
            #pragma unroll
            for (int j = 0; j < 4; ++j) acc[j][cc] = bias1[cc];
        }
        #pragma unroll 4
        for (int k = 0; k < D_IN; ++k) {
            const float* ar = &As[k * AS_STRIDE + ty * 8];
            ulonglong2 a01 = *reinterpret_cast<const ulonglong2*>(ar);
            ulonglong2 a23 = *reinterpret_cast<const ulonglong2*>(ar + 4);
            const float* wr = &W1s[k * NODE_EMB + tx];
            #pragma unroll
            for (int cc = 0; cc < 4; ++cc) {
                unsigned long long wd = bcast2(wr[32 * cc]);
                fma2(acc[0][cc], a01.x, wd);
                fma2(acc[1][cc], a01.y, wd);
                fma2(acc[2][cc], a23.x, wd);
                fma2(acc[3][cc], a23.y, wd);
            }
        }
        mlp_bar();

        #pragma unroll
        for (int cc = 0; cc < 4; ++cc) {
            int c = tx + 32 * cc;
            #pragma unroll
            for (int j = 0; j < 4; ++j) {
                float v0, v1;
                unpack2(acc[j][cc], v0, v1);
                v0 = (v0 >= 0.f) ? v0 : 0.01f * v0;
                v1 = (v1 >= 0.f) ? v1 : 0.01f * v1;
                *reinterpret_cast<unsigned long long*>(&As[c * AS_STRIDE + ty * 8 + 2 * j])
                    = pack2(v0, v1);
            }
        }
        mlp_bar();

        #pragma unroll
        for (int cc = 0; cc < 4; ++cc) {
            #pragma unroll
            for (int j = 0; j < 4; ++j) acc[j][cc] = bias2[cc];
        }
        #pragma unroll 4
        for (int k = 0; k < NODE_EMB; ++k) {
            const float* ar = &As[k * AS_STRIDE + ty * 8];
            ulonglong2 a01 = *reinterpret_cast<const ulonglong2*>(ar);
            ulonglong2 a23 = *reinterpret_cast<const ulonglong2*>(ar + 4);
            const float* wr = &W2s[k * NODE_EMB + tx];
            #pragma unroll
            for (int cc = 0; cc < 4; ++cc) {
                unsigned long long wd = bcast2(wr[32 * cc]);
                fma2(acc[0][cc], a01.x, wd);
                fma2(acc[1][cc], a01.y, wd);
                fma2(acc[2][cc], a23.x, wd);
                fma2(acc[3][cc], a23.y, wd);
            }
        }

        #pragma unroll
        for (int j = 0; j < 4; ++j) {
            int n0i = node0 + ty * 8 + 2 * j;
            #pragma unroll
            for (int cc = 0; cc < 4; ++cc) {
                float v0, v1;
                unpack2(acc[j][cc], v0, v1);
                int c = tx + 32 * cc;
                if (n0i < N)     out[(size_t)n0i * NODE_EMB + c]       = v0;
                if (n0i + 1 < N) out[(size_t)(n0i + 1) * NODE_EMB + c] = v1;
            }
        }
    }
}

// ---------------- launch ----------------
// Dependency-correct split: the scatter must COMPLETE before any MLP tile reads the
// means. So kernel A = co-resident [scatter(all E) + x-independent? no] ...
// Simplest correct schedule that still co-schedules: kernel A runs the scatter warps
// over ALL edges while MLP warps run ALL tiles — but tiles need means => WRONG.
// Correct version: fused kernel A does scatter + nothing-yet is useless. Instead we
// split the MLP: kernel A = scatter + partial MLP (x-part only, no means) is R6-8 land.
// Chosen correct schedule here: kernel A = fused (scatter warps over all E, MLP warps
// over all tiles) is INVALID; therefore we pass E to kernel A and run the MLP tiles in
// kernel B with E=0 (scatter warps exit immediately). Kernel A gets np=0 (MLP warps
// exit after weight staging). This preserves the co-residency machinery but serial
// semantics — EXCEPT kernel A's MLP warps prefetch nothing. To actually overlap within
// correctness, kernel A MLP warps compute ONLY the x-driven partial sums is the R6 path.
// Here: A = scatter-only (640thr, np=0), B = MLP-only (E=0). Equivalent to R10 serial
// but lets us A/B the arbiter overhead of the specialized kernel this round; the real
// overlap requires the hp-split which we fold in via np
// -- See kernel_launch: we run THE R6-STYLE SPLIT with co-residency:
//    A: fused_kernel(E=full, np=0)  + separate partial? (omitted)
// To keep this round SAFE and measurable, we do: A = fused(E, np=0); B = fused(0, np).
extern "C" void kernel_launch(void* const* d_in, const int* in_sizes, int n_in,
                              void* d_out, int out_size) {
    const float* x          = (const float*)d_in[0];
    const int*   edge_index = (const int*)  d_in[1];
    const float* edge_attr  = (const float*)d_in[2];
    const float* W1         = (const float*)d_in[3];
    const float* b1         = (const float*)d_in[4];
    const float* W2         = (const float*)d_in[5];
    const float* b2         = (const float*)d_in[6];
    float* out = (float*)d_out;

    int N = in_sizes[0] / NODE_EMB;
    int E = in_sizes[2] / EDGE_EMB;
    int np = (N + TILE_N - 1) / TILE_N;

    zero_kernel<<<1184, 256>>>(N);

    const int smem_bytes = (D_IN * AS_STRIDE + D_IN * NODE_EMB + NODE_EMB * NODE_EMB) * 4; // 231936
    cudaFuncSetAttribute(fused_kernel, cudaFuncAttributeMaxDynamicSharedMemorySize, smem_bytes);

    // Kernel A: scatter runs on ALL 148 SMs via its 4 warps/CTA; MLP warps exit (np=0).
    fused_kernel<<<GRID_F, THREADS, smem_bytes>>>(
        x, edge_index, reinterpret_cast<const float4*>(edge_attr),
        W1, b1, W2, b2, out, E, N, /*np=*/0);

    // Kernel B: MLP runs; scatter warps exit (E=0).
    fused_kernel<<<GRID_F, THREADS, smem_bytes>>>(
        x, edge_index, reinterpret_cast<const float4*>(edge_attr),
        W1, b1, W2, b2, out, /*E=*/0, N, np);
}

// round 12
// speedup vs baseline: 1.4406x; 1.4406x over previous
#include <cuda_runtime.h>
#include <cstdint>

#define NODE_EMB 128
#define EDGE_EMB 16
#define D_IN     160
#define N_MAX    100000
#define TILE_N   128
#define THREADS  512
#define AS_STRIDE 132
#define GRID_P   148

// ---------------- device scratch ----------------
__device__ float g_rec [N_MAX * EDGE_EMB];
__device__ float g_sent[N_MAX * EDGE_EMB];
__device__ float g_rcnt[N_MAX];
__device__ float g_scnt[N_MAX];
__device__ float g_hp  [N_MAX * NODE_EMB];   // partial h = x@W1a + b1

// ---------------- packed f32x2 helpers ----------------
__device__ __forceinline__ unsigned long long pack2(float lo, float hi) {
    unsigned long long r;
    asm("mov.b64 %0, {%1, %2};" : "=l"(r) : "f"(lo), "f"(hi));
    return r;
}
__device__ __forceinline__ unsigned long long bcast2(float v) {
    unsigned long long r;
    asm("mov.b64 %0, {%1, %1};" : "=l"(r) : "f"(v));
    return r;
}
__device__ __forceinline__ void fma2(unsigned long long& d,
                                     unsigned long long a,
                                     unsigned long long b) {
    asm("fma.rn.f32x2 %0, %1, %2, %0;" : "+l"(d) : "l"(a), "l"(b));
}
__device__ __forceinline__ void unpack2(unsigned long long v, float& lo, float& hi) {
    asm("mov.b64 {%0, %1}, %2;" : "=f"(lo), "=f"(hi) : "l"(v));
}

// ---------------- kernel 1: zero accumulators ----------------
__global__ void zero_kernel(int N) {
    int stride = gridDim.x * blockDim.x;
    int t = blockIdx.x * blockDim.x + threadIdx.x;
    int total4 = N * EDGE_EMB / 4;
    float4 z = make_float4(0.f, 0.f, 0.f, 0.f);
    for (int i = t; i < total4; i += stride) {
        reinterpret_cast<float4*>(g_rec)[i]  = z;
        reinterpret_cast<float4*>(g_sent)[i] = z;
    }
    for (int i = t; i < N; i += stride) {
        g_rcnt[i] = 0.f;
        g_scnt[i] = 0.f;
    }
}

// ---------------- kernel 2: dual scatter (R4 proven full-grid form, 243us floor) --------
__global__ void scatter_kernel(const float4* __restrict__ edge_attr4,
                               const int* __restrict__ edge_index,
                               int E) {
    int t = blockIdx.x * blockDim.x + threadIdx.x;
    int total = E * 4;
    if (t >= total) return;
    int e = t >> 2;
    int q = t & 3;
    float4 v = edge_attr4[t];
    int row = edge_index[e];
    int col = edge_index[E + e];
    float* pr = &g_rec [row * EDGE_EMB + q * 4];
    float* ps = &g_sent[col * EDGE_EMB + q * 4];
    asm volatile("red.global.add.v4.f32 [%0], {%1, %2, %3, %4};"
                 :: "l"(pr), "f"(v.x), "f"(v.y), "f"(v.z), "f"(v.w) : "memory");
    asm volatile("red.global.add.v4.f32 [%0], {%1, %2, %3, %4};"
                 :: "l"(ps), "f"(v.x), "f"(v.y), "f"(v.z), "f"(v.w) : "memory");
    if (q == 0) {
        atomicAdd(&g_rcnt[row], 1.0f);
        atomicAdd(&g_scnt[col], 1.0f);
    }
}

// ---------------- kernel 3: persistent partial MLP (x-part only; edge-independent) ------
// Runs on a forked stream CONCURRENTLY with the scatter (disjoint pipes: FMA/LDS vs LSU/L2).
__global__ __launch_bounds__(THREADS, 1)
void hp_kernel(const float* __restrict__ x,
               const float* __restrict__ W1,
               const float* __restrict__ b1,
               int N, int np) {
    extern __shared__ float smem_f[];
    float* As  = smem_f;                          // x^T [128][AS_STRIDE]
    float* W1s = As + NODE_EMB * AS_STRIDE;       // W1 rows 0..127

    int tid = threadIdx.x;
    int tx = tid & 31;
    int ty = tid >> 5;

    for (int i = tid; i < (NODE_EMB * NODE_EMB) / 4; i += THREADS)
        reinterpret_cast<float4*>(W1s)[i] = reinterpret_cast<const float4*>(W1)[i];

    unsigned long long bias[4];
    #pragma unroll
    for (int cc = 0; cc < 4; ++cc) bias[cc] = bcast2(b1[tx + 32 * cc]);

    for (int tile = blockIdx.x; tile < np; tile += GRID_P) {
        int node0 = tile * TILE_N;
        __syncthreads();
        for (int idx = tid; idx < TILE_N * NODE_EMB; idx += THREADS) {
            int nl = idx >> 7;
            int k  = idx & 127;
            int n  = node0 + nl;
            As[k * AS_STRIDE + nl] = (n < N) ? x[(size_t)n * NODE_EMB + k] : 0.f;
        }
        __syncthreads();

        unsigned long long acc[4][4];
        #pragma unroll
        for (int cc = 0; cc < 4; ++cc) {
            #pragma unroll
            for (int j = 0; j < 4; ++j) acc[j][cc] = bias[cc];
        }
        #pragma unroll 4
        for (int k = 0; k < NODE_EMB; ++k) {
            const float* ar = &As[k * AS_STRIDE + ty * 8];
            ulonglong2 a01 = *reinterpret_cast<const ulonglong2*>(ar);
            ulonglong2 a23 = *reinterpret_cast<const ulonglong2*>(ar + 4);
            const float* wr = &W1s[k * NODE_EMB + tx];
            #pragma unroll
            for (int cc = 0; cc < 4; ++cc) {
                unsigned long long wd = bcast2(wr[32 * cc]);
                fma2(acc[0][cc], a01.x, wd);
                fma2(acc[1][cc], a01.y, wd);
                fma2(acc[2][cc], a23.x, wd);
                fma2(acc[3][cc], a23.y, wd);
            }
        }

        #pragma unroll
        for (int j = 0; j < 4; ++j) {
            int n0i = node0 + ty * 8 + 2 * j;
            #pragma unroll
            for (int cc = 0; cc < 4; ++cc) {
                float v0, v1;
                unpack2(acc[j][cc], v0, v1);
                int c = tx + 32 * cc;
                if (n0i < N)     g_hp[(size_t)n0i * NODE_EMB + c]       = v0;
                if (n0i + 1 < N) g_hp[(size_t)(n0i + 1) * NODE_EMB + c] = v1;
            }
        }
    }
}

// ---------------- kernel 4: persistent finish (means + 32k + ReLU + phase2) ----------------
__global__ __launch_bounds__(THREADS, 1)
void finish_kernel(const float* __restrict__ W1,
                   const float* __restrict__ W2,
                   const float* __restrict__ b2,
                   float* __restrict__ out,
                   int N, int np) {
    extern __shared__ float smem_f[];
    float* Hs   = smem_f;                              // h^T [128][AS_STRIDE]
    float* Ms   = Hs + NODE_EMB * AS_STRIDE;           // means^T [32][AS_STRIDE]
    float* W1bs = Ms + 2 * EDGE_EMB * AS_STRIDE;       // W1 rows 128..159
    float* W2s  = W1bs + 2 * EDGE_EMB * NODE_EMB;      // [128][128]

    int tid = threadIdx.x;
    int tx = tid & 31;
    int ty = tid >> 5;

    for (int i = tid; i < (2 * EDGE_EMB * NODE_EMB) / 4; i += THREADS)
        reinterpret_cast<float4*>(W1bs)[i] =
            reinterpret_cast<const float4*>(W1 + NODE_EMB * NODE_EMB)[i];
    for (int i = tid; i < (NODE_EMB * NODE_EMB) / 4; i += THREADS)
        reinterpret_cast<float4*>(W2s)[i] = reinterpret_cast<const float4*>(W2)[i];

    unsigned long long bias2[4];
    #pragma unroll
    for (int cc = 0; cc < 4; ++cc) bias2[cc] = bcast2(b2[tx + 32 * cc]);

    for (int tile = blockIdx.x; tile < np; tile += GRID_P) {
        int node0 = tile * TILE_N;
        __syncthreads();

        for (int idx = tid; idx < TILE_N * 2 * EDGE_EMB; idx += THREADS) {
            int nl = idx >> 5;
            int k  = idx & 31;
            int n  = node0 + nl;
            float v = 0.f;
            if (n < N) {
                if (k < EDGE_EMB) v = g_rec [(size_t)n * EDGE_EMB + k]              / fmaxf(g_rcnt[n], 1.f);
                else              v = g_sent[(size_t)n * EDGE_EMB + (k - EDGE_EMB)] / fmaxf(g_scnt[n], 1.f);
            }
            Ms[k * AS_STRIDE + nl] = v;
        }
        __syncthreads();

        unsigned long long acc[4][4];
        #pragma unroll
        for (int j = 0; j < 4; ++j) {
            int n0i = node0 + ty * 8 + 2 * j;
            #pragma unroll
            for (int cc = 0; cc < 4; ++cc) {
                int c = tx + 32 * cc;
                float lo = (n0i < N)     ? g_hp[(size_t)n0i * NODE_EMB + c]       : 0.f;
                float hi = (n0i + 1 < N) ? g_hp[(size_t)(n0i + 1) * NODE_EMB + c] : 0.f;
                acc[j][cc] = pack2(lo, hi);
            }
        }

        #pragma unroll 4
        for (int k = 0; k < 2 * EDGE_EMB; ++k) {
            const float* ar = &Ms[k * AS_STRIDE + ty * 8];
            ulonglong2 a01 = *reinterpret_cast<const ulonglong2*>(ar);
            ulonglong2 a23 = *reinterpret_cast<const ulonglong2*>(ar + 4);
            const float* wr = &W1bs[k * NODE_EMB + tx];
            #pragma unroll
            for (int cc = 0; cc < 4; ++cc) {
                unsigned long long wd = bcast2(wr[32 * cc]);
                fma2(acc[0][cc], a01.x, wd);
                fma2(acc[1][cc], a01.y, wd);
                fma2(acc[2][cc], a23.x, wd);
                fma2(acc[3][cc], a23.y, wd);
            }
        }

        #pragma unroll
        for (int cc = 0; cc < 4; ++cc) {
            int c = tx + 32 * cc;
            #pragma unroll
            for (int j = 0; j < 4; ++j) {
                float v0, v1;
                unpack2(acc[j][cc], v0, v1);
                v0 = (v0 >= 0.f) ? v0 : 0.01f * v0;
                v1 = (v1 >= 0.f) ? v1 : 0.01f * v1;
                *reinterpret_cast<unsigned long long*>(&Hs[c * AS_STRIDE + ty * 8 + 2 * j])
                    = pack2(v0, v1);
            }
        }
        __syncthreads();

        #pragma unroll
        for (int cc = 0; cc < 4; ++cc) {
            #pragma unroll
            for (int j = 0; j < 4; ++j) acc[j][cc] = bias2[cc];
        }
        #pragma unroll 4
        for (int k = 0; k < NODE_EMB; ++k) {
            const float* ar = &Hs[k * AS_STRIDE + ty * 8];
            ulonglong2 a01 = *reinterpret_cast<const ulonglong2*>(ar);
            ulonglong2 a23 = *reinterpret_cast<const ulonglong2*>(ar + 4);
            const float* wr = &W2s[k * NODE_EMB + tx];
            #pragma unroll
            for (int cc = 0; cc < 4; ++cc) {
                unsigned long long wd = bcast2(wr[32 * cc]);
                fma2(acc[0][cc], a01.x, wd);
                fma2(acc[1][cc], a01.y, wd);
                fma2(acc[2][cc], a23.x, wd);
                fma2(acc[3][cc], a23.y, wd);
            }
        }

        #pragma unroll
        for (int j = 0; j < 4; ++j) {
            int n0i = node0 + ty * 8 + 2 * j;
            #pragma unroll
            for (int cc = 0; cc < 4; ++cc) {
                float v0, v1;
                unpack2(acc[j][cc], v0, v1);
                int c = tx + 32 * cc;
                if (n0i < N)     out[(size_t)n0i * NODE_EMB + c]       = v0;
                if (n0i + 1 < N) out[(size_t)(n0i + 1) * NODE_EMB + c] = v1;
            }
        }
    }
}

// ---------------- launch: graph-level fork-join ----------------
// Default stream: e0 -> zero -> scatter -> (wait e1) -> finish
// Side stream B:  (wait e0) -> hp        -> e1
// hp is edge-independent so it legally runs concurrent with zero+scatter.
// Stream/events created once (host-side objects, no device memory) during the
// uncaptured correctness call; reused identically every call (deterministic).
extern "C" void kernel_launch(void* const* d_in, const int* in_sizes, int n_in,
                              void* d_out, int out_size) {
    const float* x          = (const float*)d_in[0];
    const int*   edge_index = (const int*)  d_in[1];
    const float* edge_attr  = (const float*)d_in[2];
    const float* W1         = (const float*)d_in[3];
    const float* b1         = (const float*)d_in[4];
    const float* W2         = (const float*)d_in[5];
    const float* b2         = (const float*)d_in[6];
    float* out = (float*)d_out;

    int N = in_sizes[0] / NODE_EMB;
    int E = in_sizes[2] / EDGE_EMB;
    int np = (N + TILE_N - 1) / TILE_N;

    static cudaStream_t sB = nullptr;
    static cudaEvent_t e0 = nullptr, e1 = nullptr;
    static bool attrs_set = false;
    if (sB == nullptr) {
        cudaStreamCreateWithFlags(&sB, cudaStreamNonBlocking);
        cudaEventCreateWithFlags(&e0, cudaEventDisableTiming);
        cudaEventCreateWithFlags(&e1, cudaEventDisableTiming);
    }
    const int hp_smem  = (NODE_EMB * AS_STRIDE + NODE_EMB * NODE_EMB) * 4;        // 133120
    const int fin_smem = (NODE_EMB * AS_STRIDE + 2 * EDGE_EMB * AS_STRIDE
                          + 2 * EDGE_EMB * NODE_EMB + NODE_EMB * NODE_EMB) * 4;   // 166400
    if (!attrs_set) {
        cudaFuncSetAttribute(hp_kernel,     cudaFuncAttributeMaxDynamicSharedMemorySize, hp_smem);
        cudaFuncSetAttribute(finish_kernel, cudaFuncAttributeMaxDynamicSharedMemorySize, fin_smem);
        attrs_set = true;
    }

    // Fork
    cudaEventRecord(e0, 0);
    cudaStreamWaitEvent(sB, e0, 0);

    // Branch B: edge-independent partial MLP
    hp_kernel<<<GRID_P, THREADS, hp_smem, sB>>>(x, W1, b1, N, np);
    cudaEventRecord(e1, sB);

    // Main branch: zero + scatter
    zero_kernel<<<1184, 256>>>(N);
    int total = E * 4;
    scatter_kernel<<<(total + 255) / 256, 256>>>(
        reinterpret_cast<const float4*>(edge_attr), edge_index, E);

    // Join, then finish
    cudaStreamWaitEvent(0, e1, 0);
    finish_kernel<<<GRID_P, THREADS, fin_smem>>>(W1, W2, b2, out, N, np);
}

// round 13
// speedup vs baseline: 1.4694x; 1.0200x over previous
#include <cuda_runtime.h>
#include <cstdint>

#define NODE_EMB 128
#define EDGE_EMB 16
#define D_IN     160
#define N_MAX    100000
#define TILE_N   128
#define THREADS  512
#define FIN_T    1024
#define AS_STRIDE 132
#define GRID_P   148

// ---------------- device scratch ----------------
__device__ float g_rec [N_MAX * EDGE_EMB];
__device__ float g_sent[N_MAX * EDGE_EMB];
__device__ float g_rcnt[N_MAX];
__device__ float g_scnt[N_MAX];
__device__ float g_hp  [N_MAX * NODE_EMB];   // partial h = x@W1a + b1

// ---------------- packed f32x2 helpers ----------------
__device__ __forceinline__ unsigned long long pack2(float lo, float hi) {
    unsigned long long r;
    asm("mov.b64 %0, {%1, %2};" : "=l"(r) : "f"(lo), "f"(hi));
    return r;
}
__device__ __forceinline__ unsigned long long bcast2(float v) {
    unsigned long long r;
    asm("mov.b64 %0, {%1, %1};" : "=l"(r) : "f"(v));
    return r;
}
__device__ __forceinline__ void fma2(unsigned long long& d,
                                     unsigned long long a,
                                     unsigned long long b) {
    asm("fma.rn.f32x2 %0, %1, %2, %0;" : "+l"(d) : "l"(a), "l"(b));
}
__device__ __forceinline__ void unpack2(unsigned long long v, float& lo, float& hi) {
    asm("mov.b64 {%0, %1}, %2;" : "=f"(lo), "=f"(hi) : "l"(v));
}

// ---------------- kernel 1: zero accumulators ----------------
__global__ void zero_kernel(int N) {
    int stride = gridDim.x * blockDim.x;
    int t = blockIdx.x * blockDim.x + threadIdx.x;
    int total4 = N * EDGE_EMB / 4;
    float4 z = make_float4(0.f, 0.f, 0.f, 0.f);
    for (int i = t; i < total4; i += stride) {
        reinterpret_cast<float4*>(g_rec)[i]  = z;
        reinterpret_cast<float4*>(g_sent)[i] = z;
    }
    for (int i = t; i < N; i += stride) {
        g_rcnt[i] = 0.f;
        g_scnt[i] = 0.f;
    }
}

// ---------------- kernel 2: dual scatter (R4 proven full-grid form) ----------------
__global__ void scatter_kernel(const float4* __restrict__ edge_attr4,
                               const int* __restrict__ edge_index,
                               int E) {
    int t = blockIdx.x * blockDim.x + threadIdx.x;
    int total = E * 4;
    if (t >= total) return;
    int e = t >> 2;
    int q = t & 3;
    float4 v = edge_attr4[t];
    int row = edge_index[e];
    int col = edge_index[E + e];
    float* pr = &g_rec [row * EDGE_EMB + q * 4];
    float* ps = &g_sent[col * EDGE_EMB + q * 4];
    asm volatile("red.global.add.v4.f32 [%0], {%1, %2, %3, %4};"
                 :: "l"(pr), "f"(v.x), "f"(v.y), "f"(v.z), "f"(v.w) : "memory");
    asm volatile("red.global.add.v4.f32 [%0], {%1, %2, %3, %4};"
                 :: "l"(ps), "f"(v.x), "f"(v.y), "f"(v.z), "f"(v.w) : "memory");
    if (q == 0) {
        atomicAdd(&g_rcnt[row], 1.0f);
        atomicAdd(&g_scnt[col], 1.0f);
    }
}

// ---------------- kernel 3: persistent partial MLP (x-part only; edge-independent) ------
__global__ __launch_bounds__(THREADS, 1)
void hp_kernel(const float* __restrict__ x,
               const float* __restrict__ W1,
               const float* __restrict__ b1,
               int N, int np) {
    extern __shared__ float smem_f[];
    float* As  = smem_f;                          // x^T [128][AS_STRIDE]
    float* W1s = As + NODE_EMB * AS_STRIDE;       // W1 rows 0..127

    int tid = threadIdx.x;
    int tx = tid & 31;
    int ty = tid >> 5;

    for (int i = tid; i < (NODE_EMB * NODE_EMB) / 4; i += THREADS)
        reinterpret_cast<float4*>(W1s)[i] = reinterpret_cast<const float4*>(W1)[i];

    unsigned long long bias[4];
    #pragma unroll
    for (int cc = 0; cc < 4; ++cc) bias[cc] = bcast2(b1[tx + 32 * cc]);

    for (int tile = blockIdx.x; tile < np; tile += GRID_P) {
        int node0 = tile * TILE_N;
        __syncthreads();
        for (int idx = tid; idx < TILE_N * NODE_EMB; idx += THREADS) {
            int nl = idx >> 7;
            int k  = idx & 127;
            int n  = node0 + nl;
            As[k * AS_STRIDE + nl] = (n < N) ? x[(size_t)n * NODE_EMB + k] : 0.f;
        }
        __syncthreads();

        unsigned long long acc[4][4];
        #pragma unroll
        for (int cc = 0; cc < 4; ++cc) {
            #pragma unroll
            for (int j = 0; j < 4; ++j) acc[j][cc] = bias[cc];
        }
        #pragma unroll 4
        for (int k = 0; k < NODE_EMB; ++k) {
            const float* ar = &As[k * AS_STRIDE + ty * 8];
            ulonglong2 a01 = *reinterpret_cast<const ulonglong2*>(ar);
            ulonglong2 a23 = *reinterpret_cast<const ulonglong2*>(ar + 4);
            const float* wr = &W1s[k * NODE_EMB + tx];
            #pragma unroll
            for (int cc = 0; cc < 4; ++cc) {
                unsigned long long wd = bcast2(wr[32 * cc]);
                fma2(acc[0][cc], a01.x, wd);
                fma2(acc[1][cc], a01.y, wd);
                fma2(acc[2][cc], a23.x, wd);
                fma2(acc[3][cc], a23.y, wd);
            }
        }

        #pragma unroll
        for (int j = 0; j < 4; ++j) {
            int n0i = node0 + ty * 8 + 2 * j;
            #pragma unroll
            for (int cc = 0; cc < 4; ++cc) {
                float v0, v1;
                unpack2(acc[j][cc], v0, v1);
                int c = tx + 32 * cc;
                if (n0i < N)     g_hp[(size_t)n0i * NODE_EMB + c]       = v0;
                if (n0i + 1 < N) g_hp[(size_t)(n0i + 1) * NODE_EMB + c] = v1;
            }
        }
    }
}

// ---------------- kernel 4: persistent finish, 1024 threads (32 warps) ----------------
// Warp wid: node group wy = wid>>1 (8 nodes), col half wc = wid&1 (cols tx+64wc, tx+32+64wc).
// Per thread: 4 node-pairs x 2 cols (16 acc regs). 8 warps/SMSP hides LDS->FMA latency.
__global__ __launch_bounds__(FIN_T, 1)
void finish_kernel(const float* __restrict__ W1,
                   const float* __restrict__ W2,
                   const float* __restrict__ b2,
                   float* __restrict__ out,
                   int N, int np) {
    extern __shared__ float smem_f[];
    float* Hs   = smem_f;                              // h^T [128][AS_STRIDE]
    float* Ms   = Hs + NODE_EMB * AS_STRIDE;           // means^T [32][AS_STRIDE]
    float* W1bs = Ms + 2 * EDGE_EMB * AS_STRIDE;       // W1 rows 128..159
    float* W2s  = W1bs + 2 * EDGE_EMB * NODE_EMB;      // [128][128]

    int tid = threadIdx.x;
    int tx = tid & 31;
    int wid = tid >> 5;
    int wy = wid >> 1;          // node group: nodes [wy*8, wy*8+8)
    int wc = wid & 1;           // col half
    int c0 = tx + 64 * wc;      // cols c0 and c0+32

    for (int i = tid; i < (2 * EDGE_EMB * NODE_EMB) / 4; i += FIN_T)
        reinterpret_cast<float4*>(W1bs)[i] =
            reinterpret_cast<const float4*>(W1 + NODE_EMB * NODE_EMB)[i];
    for (int i = tid; i < (NODE_EMB * NODE_EMB) / 4; i += FIN_T)
        reinterpret_cast<float4*>(W2s)[i] = reinterpret_cast<const float4*>(W2)[i];

    unsigned long long bias2[2];
    bias2[0] = bcast2(b2[c0]);
    bias2[1] = bcast2(b2[c0 + 32]);

    for (int tile = blockIdx.x; tile < np; tile += GRID_P) {
        int node0 = tile * TILE_N;
        __syncthreads();

        for (int idx = tid; idx < TILE_N * 2 * EDGE_EMB; idx += FIN_T) {
            int nl = idx >> 5;
            int k  = idx & 31;
            int n  = node0 + nl;
            float v = 0.f;
            if (n < N) {
                if (k < EDGE_EMB) v = g_rec [(size_t)n * EDGE_EMB + k]              / fmaxf(g_rcnt[n], 1.f);
                else              v = g_sent[(size_t)n * EDGE_EMB + (k - EDGE_EMB)] / fmaxf(g_scnt[n], 1.f);
            }
            Ms[k * AS_STRIDE + nl] = v;
        }
        __syncthreads();

        // Init acc from hp (coalesced LDG)
        unsigned long long acc[4][2];
        #pragma unroll
        for (int j = 0; j < 4; ++j) {
            int n0i = node0 + wy * 8 + 2 * j;
            #pragma unroll
            for (int cc = 0; cc < 2; ++cc) {
                int c = c0 + 32 * cc;
                float lo = (n0i < N)     ? g_hp[(size_t)n0i * NODE_EMB + c]       : 0.f;
                float hi = (n0i + 1 < N) ? g_hp[(size_t)(n0i + 1) * NODE_EMB + c] : 0.f;
                acc[j][cc] = pack2(lo, hi);
            }
        }

        // Mean-driven k-iterations (32)
        #pragma unroll 4
        for (int k = 0; k < 2 * EDGE_EMB; ++k) {
            const float* ar = &Ms[k * AS_STRIDE + wy * 8];
            ulonglong2 a01 = *reinterpret_cast<const ulonglong2*>(ar);
            ulonglong2 a23 = *reinterpret_cast<const ulonglong2*>(ar + 4);
            const float* wr = &W1bs[k * NODE_EMB + c0];
            #pragma unroll
            for (int cc = 0; cc < 2; ++cc) {
                unsigned long long wd = bcast2(wr[32 * cc]);
                fma2(acc[0][cc], a01.x, wd);
                fma2(acc[1][cc], a01.y, wd);
                fma2(acc[2][cc], a23.x, wd);
                fma2(acc[3][cc], a23.y, wd);
            }
        }

        // LeakyReLU + store h^T[c][node]
        #pragma unroll
        for (int cc = 0; cc < 2; ++cc) {
            int c = c0 + 32 * cc;
            #pragma unroll
            for (int j = 0; j < 4; ++j) {
                float v0, v1;
                unpack2(acc[j][cc], v0, v1);
                v0 = (v0 >= 0.f) ? v0 : 0.01f * v0;
                v1 = (v1 >= 0.f) ? v1 : 0.01f * v1;
                *reinterpret_cast<unsigned long long*>(&Hs[c * AS_STRIDE + wy * 8 + 2 * j])
                    = pack2(v0, v1);
            }
        }
        __syncthreads();

        // Phase 2: out = h @ W2 + b2
        #pragma unroll
        for (int cc = 0; cc < 2; ++cc) {
            #pragma unroll
            for (int j = 0; j < 4; ++j) acc[j][cc] = bias2[cc];
        }
        #pragma unroll 4
        for (int k = 0; k < NODE_EMB; ++k) {
            const float* ar = &Hs[k * AS_STRIDE + wy * 8];
            ulonglong2 a01 = *reinterpret_cast<const ulonglong2*>(ar);
            ulonglong2 a23 = *reinterpret_cast<const ulonglong2*>(ar + 4);
            const float* wr = &W2s[k * NODE_EMB + c0];
            #pragma unroll
            for (int cc = 0; cc < 2; ++cc) {
                unsigned long long wd = bcast2(wr[32 * cc]);
                fma2(acc[0][cc], a01.x, wd);
                fma2(acc[1][cc], a01.y, wd);
                fma2(acc[2][cc], a23.x, wd);
                fma2(acc[3][cc], a23.y, wd);
            }
        }

        #pragma unroll
        for (int j = 0; j < 4; ++j) {
            int n0i = node0 + wy * 8 + 2 * j;
            #pragma unroll
            for (int cc = 0; cc < 2; ++cc) {
                float v0, v1;
                unpack2(acc[j][cc], v0, v1);
                int c = c0 + 32 * cc;
                if (n0i < N)     out[(size_t)n0i * NODE_EMB + c]       = v0;
                if (n0i + 1 < N) out[(size_t)(n0i + 1) * NODE_EMB + c] = v1;
            }
        }
    }
}

// ---------------- launch: graph-level fork-join ----------------
extern "C" void kernel_launch(void* const* d_in, const int* in_sizes, int n_in,
                              void* d_out, int out_size) {
    const float* x          = (const float*)d_in[0];
    const int*   edge_index = (const int*)  d_in[1];
    const float* edge_attr  = (const float*)d_in[2];
    const float* W1         = (const float*)d_in[3];
    const float* b1         = (const float*)d_in[4];
    const float* W2         = (const float*)d_in[5];
    const float* b2         = (const float*)d_in[6];
    float* out = (float*)d_out;

    int N = in_sizes[0] / NODE_EMB;
    int E = in_sizes[2] / EDGE_EMB;
    int np = (N + TILE_N - 1) / TILE_N;

    static cudaStream_t sB = nullptr;
    static cudaEvent_t e0 = nullptr, e1 = nullptr;
    static bool attrs_set = false;
    if (sB == nullptr) {
        cudaStreamCreateWithFlags(&sB, cudaStreamNonBlocking);
        cudaEventCreateWithFlags(&e0, cudaEventDisableTiming);
        cudaEventCreateWithFlags(&e1, cudaEventDisableTiming);
    }
    const int hp_smem  = (NODE_EMB * AS_STRIDE + NODE_EMB * NODE_EMB) * 4;        // 133120
    const int fin_smem = (NODE_EMB * AS_STRIDE + 2 * EDGE_EMB * AS_STRIDE
                          + 2 * EDGE_EMB * NODE_EMB + NODE_EMB * NODE_EMB) * 4;   // 166400
    if (!attrs_set) {
        cudaFuncSetAttribute(hp_kernel,     cudaFuncAttributeMaxDynamicSharedMemorySize, hp_smem);
        cudaFuncSetAttribute(finish_kernel, cudaFuncAttributeMaxDynamicSharedMemorySize, fin_smem);
        attrs_set = true;
    }

    // Fork
    cudaEventRecord(e0, 0);
    cudaStreamWaitEvent(sB, e0, 0);

    // Branch B: edge-independent partial MLP
    hp_kernel<<<GRID_P, THREADS, hp_smem, sB>>>(x, W1, b1, N, np);
    cudaEventRecord(e1, sB);

    // Main branch: zero + scatter
    zero_kernel<<<1184, 256>>>(N);
    int total = E * 4;
    scatter_kernel<<<(total + 255) / 256, 256>>>(
        reinterpret_cast<const float4*>(edge_attr), edge_index, E);

    // Join, then finish
    cudaStreamWaitEvent(0, e1, 0);
    finish_kernel<<<GRID_P, FIN_T, fin_smem>>>(W1, W2, b2, out, N, np);
}